// round 11
// baseline (speedup 1.0000x reference)
#include <cuda_runtime.h>
#include <cuda_fp16.h>
#include <cstdint>

#define DK    4096
#define NCOL  64
#define KC    32
#define NCH   128                  // chunks per full-K sweep
#define MAX_M 16384
#define MT16  1024                 // total m16 row-tiles
#define WSC   4096.0f
#define WSCI  (1.0f / 4096.0f)

// ---------------- device scratch ----------------
__device__ uint16_t     g_Whf[256 * 2 * 4 * 32 * 8];  // fp16 hi/lo B-fragments
__device__ unsigned int g_absmax_bits;
__device__ unsigned int g_barcnt;

__constant__ float L_C[16] = {
    -1.0f, -0.6961928009986877f, -0.5250730514526367f, -0.39491748809814453f,
    -0.28444138169288635f, -0.18477343022823334f, -0.09105003625154495f, 0.0f,
    0.07958029955625534f, 0.16093020141124725f, 0.24611230194568634f,
    0.33791524171829224f, 0.44070982933044434f, 0.5626170039176941f,
    0.7229568362236023f, 1.0f };
__constant__ float MID_C[15] = {
    -0.8480964004993439f, -0.6106329262256622f, -0.4599952697753906f,
    -0.33967943489551544f, -0.23460740596055984f, -0.13791173323988914f,
    -0.045525018125772476f, 0.03979014977812767f, 0.1202552504837513f,
    0.2035212516784668f, 0.2920137718319893f, 0.3893125355243683f,
    0.5016634166240692f, 0.6427869200706482f, 0.8614784181118011f };

// ---------------- helpers ----------------
__device__ __forceinline__ void cp_async16(uint32_t dst, const void* src) {
    asm volatile("cp.async.cg.shared.global [%0], [%1], 16;" :: "r"(dst), "l"(src));
}
#define CP_COMMIT() asm volatile("cp.async.commit_group;")
#define CP_WAIT0()  asm volatile("cp.async.wait_group 0;")

__device__ __forceinline__ void lds128(uint4& v, uint32_t a) {
    asm volatile("ld.shared.v4.b32 {%0,%1,%2,%3}, [%4];"
                 : "=r"(v.x), "=r"(v.y), "=r"(v.z), "=r"(v.w) : "r"(a));
}
__device__ __forceinline__ float2 lds64f(uint32_t a) {
    float2 v;
    asm volatile("ld.shared.v2.f32 {%0,%1}, [%2];" : "=f"(v.x), "=f"(v.y) : "r"(a));
    return v;
}

__device__ __forceinline__ uint32_t f16x2_rn(float a, float b) {
    uint32_t r;
    asm("cvt.rn.f16x2.f32 %0, %1, %2;" : "=r"(r) : "f"(b), "f"(a));
    return r;
}
__device__ __forceinline__ void f16x2_unpack(uint32_t p, float& lo, float& hi) {
    asm("{.reg .f16 l, h; mov.b32 {l, h}, %2;"
        " cvt.f32.f16 %0, l; cvt.f32.f16 %1, h;}"
        : "=f"(lo), "=f"(hi) : "r"(p));
}
__device__ __forceinline__ void split_pair(float2 x, uint32_t& h, uint32_t& l) {
    h = f16x2_rn(x.x, x.y);
    float hx, hy;
    f16x2_unpack(h, hx, hy);
    l = f16x2_rn(x.x - hx, x.y - hy);
}

__device__ __forceinline__ void mma16(float4& d, uint32_t a0, uint32_t a1,
                                      uint32_t a2, uint32_t a3,
                                      uint32_t b0, uint32_t b1) {
    asm volatile(
        "mma.sync.aligned.m16n8k16.row.col.f32.f16.f16.f32 "
        "{%0,%1,%2,%3},{%4,%5,%6,%7},{%8,%9},{%0,%1,%2,%3};"
        : "+f"(d.x), "+f"(d.y), "+f"(d.z), "+f"(d.w)
        : "r"(a0), "r"(a1), "r"(a2), "r"(a3), "r"(b0), "r"(b1));
}

__device__ __forceinline__ float nf4_bs(float v) {
    int idx = (v > MID_C[7]) ? 8 : 0;
    idx += (v > MID_C[idx + 3]) ? 4 : 0;
    idx += (v > MID_C[idx + 1]) ? 2 : 0;
    idx += (v > MID_C[idx]) ? 1 : 0;
    return L_C[idx];
}

// ---------------- kernel 1: W -> fp16 hi/lo fragments; reset globals ----------------
__global__ void k_w(const float* __restrict__ Bm, const float* __restrict__ A,
                    const float* __restrict__ ri) {
    __shared__ float sA[64 * 64];
    __shared__ float sB[4 * 64];
    __shared__ float cs[64];
    __shared__ int cnt;
    int tx = threadIdx.x, ty = threadIdx.y;
    int tid = ty * 64 + tx;
    int k = blockIdx.x * 4 + ty;            // 0..4095

    if (blockIdx.x == 0 && tid == 0) {
        g_absmax_bits = 0u;
        g_barcnt = 0u;
    }

    if (tid == 0) cnt = 0;
    __syncthreads();
    if (tid < 64) {
        float s = 1.0f / (1.0f + expf(-ri[tid]));
        int a = (s > 0.1f) ? 1 : 0;
        cs[tid] = (float)a;
        atomicAdd(&cnt, a);
    }

#pragma unroll
    for (int t = 0; t < 16; t++) sA[tid + t * 256] = A[tid + t * 256];
    sB[tid] = Bm[blockIdx.x * 256 + tid];
    __syncthreads();

    float colscale = 0.25f * WSC * ((cnt > 0) ? cs[tx] : 1.0f);

    float acc = 0.0f;
#pragma unroll 8
    for (int r = 0; r < 64; r++)
        acc = fmaf(sB[ty * 64 + r], sA[r * 64 + tx], acc);
    float w = acc * colscale;

    __half hh = __float2half_rn(w);
    float  hf = __half2float(hh);
    __half hl = __float2half_rn(w - hf);

    int n = tx;
    int k16 = k >> 4, kr = k & 15;
    int reg = kr >> 3;
    int l   = ((n & 7) << 2) | ((kr & 7) >> 1);
    int grp = n >> 4;
    int ntp = (n >> 3) & 1;
    size_t base = ((((size_t)(k16 * 2 + 0) * 4 + grp) * 32 + l) * 8)
                  + (size_t)(ntp * 2 + reg) * 2 + (kr & 1);
    g_Whf[base]                      = __half_as_ushort(hh);
    g_Whf[base + (size_t)4 * 32 * 8] = __half_as_ushort(hl);
}

// ---------------- kernel 2: register-resident GEMM + absmax + quantize ----------------
#define SMA_SZ 16128                 // 112 rows * 144B (max NT=7)
#define SMB_SZ 8192
#define SM_TOTAL (2 * SMA_SZ + 2 * SMB_SZ)

template <int NT>
__device__ __forceinline__ void gemm_body(const float* __restrict__ x,
                                          float* __restrict__ out,
                                          const float* __restrict__ qs,
                                          int t0, uint32_t sbA, uint32_t sbB,
                                          unsigned int nblk) {
    int tid = threadIdx.x;
    int wid = tid >> 5, l = tid & 31;
    int r_in = l >> 2, cq = l & 3;
    const char* wsrc = (const char*)g_Whf;
    const float* xblk = x + (size_t)t0 * 16 * DK;

    float4 C[NT][2], S[NT][2];
#pragma unroll
    for (int a = 0; a < NT; a++)
#pragma unroll
        for (int b = 0; b < 2; b++) {
            C[a][b] = make_float4(0.f, 0.f, 0.f, 0.f);
            S[a][b] = make_float4(0.f, 0.f, 0.f, 0.f);
        }

    // prologue: chunk 0 into buffer 0
#pragma unroll
    for (int i = 0; i < NT; i++) {
        int idx = i * 128 + tid;
        int row = idx >> 3, q = idx & 7;
        cp_async16(sbA + (uint32_t)(row * 144 + q * 16),
                   xblk + (size_t)row * DK + q * 4);
    }
#pragma unroll
    for (int i = 0; i < 4; i++) {
        int idx = i * 128 + tid;
        cp_async16(sbB + (uint32_t)(idx * 16), wsrc + (size_t)idx * 16);
    }
    CP_COMMIT();

#pragma unroll 1
    for (int c = 0; c < NCH; c++) {
        int buf = c & 1;
        CP_WAIT0();
        __syncthreads();

        if (c + 1 < NCH) {
            int nb = (c + 1) & 1;
            int k0 = (c + 1) * KC;
            uint32_t aoff = sbA + (uint32_t)(nb * SMA_SZ);
            uint32_t boff = sbB + (uint32_t)(nb * SMB_SZ);
            const char* bs = wsrc + (size_t)(c + 1) * SMB_SZ;
#pragma unroll
            for (int i = 0; i < NT; i++) {
                int idx = i * 128 + tid;
                int row = idx >> 3, q = idx & 7;
                cp_async16(aoff + (uint32_t)(row * 144 + q * 16),
                           xblk + (size_t)row * DK + k0 + q * 4);
            }
#pragma unroll
            for (int i = 0; i < 4; i++) {
                int idx = i * 128 + tid;
                cp_async16(boff + (uint32_t)(idx * 16), bs + (size_t)idx * 16);
            }
            CP_COMMIT();
        }

        uint32_t ab = sbA + (uint32_t)(buf * SMA_SZ);
        uint32_t bb = sbB + (uint32_t)(buf * SMB_SZ);

#pragma unroll
        for (int ks = 0; ks < 2; ks++) {
            uint4 BH, BL;
            lds128(BH, bb + (uint32_t)((((ks * 2 + 0) * 4 + wid) * 32 + l) * 16));
            lds128(BL, bb + (uint32_t)((((ks * 2 + 1) * 4 + wid) * 32 + l) * 16));

#pragma unroll
            for (int rt = 0; rt < NT; rt++) {
                uint32_t ra = ab + (uint32_t)((rt * 16 + r_in) * 144
                                              + (ks * 16 + cq * 2) * 4);
                float2 p0 = lds64f(ra);
                float2 p1 = lds64f(ra + 8 * 144);
                float2 p2 = lds64f(ra + 32);
                float2 p3 = lds64f(ra + 8 * 144 + 32);

                uint32_t ah0, al0, ah1, al1, ah2, al2, ah3, al3;
                split_pair(p0, ah0, al0);
                split_pair(p1, ah1, al1);
                split_pair(p2, ah2, al2);
                split_pair(p3, ah3, al3);

                mma16(C[rt][0], ah0, ah1, ah2, ah3, BH.x, BH.y);
                mma16(C[rt][1], ah0, ah1, ah2, ah3, BH.z, BH.w);
                mma16(C[rt][0], ah0, ah1, ah2, ah3, BL.x, BL.y);
                mma16(C[rt][1], ah0, ah1, ah2, ah3, BL.z, BL.w);
                mma16(C[rt][0], al0, al1, al2, al3, BH.x, BH.y);
                mma16(C[rt][1], al0, al1, al2, al3, BH.z, BH.w);
            }
        }

        if ((c & 15) == 15) {
#pragma unroll
            for (int a = 0; a < NT; a++)
#pragma unroll
                for (int b = 0; b < 2; b++) {
                    S[a][b].x += C[a][b].x; S[a][b].y += C[a][b].y;
                    S[a][b].z += C[a][b].z; S[a][b].w += C[a][b].w;
                    C[a][b] = make_float4(0.f, 0.f, 0.f, 0.f);
                }
        }
    }

    // ---- local absmax from registers (apply WSCI unscale) ----
    float mx = 0.0f;
#pragma unroll
    for (int a = 0; a < NT; a++)
#pragma unroll
        for (int b = 0; b < 2; b++) {
            S[a][b].x *= WSCI; S[a][b].y *= WSCI;
            S[a][b].z *= WSCI; S[a][b].w *= WSCI;
            mx = fmaxf(mx, fmaxf(fmaxf(fabsf(S[a][b].x), fabsf(S[a][b].y)),
                                 fmaxf(fabsf(S[a][b].z), fabsf(S[a][b].w))));
        }
#pragma unroll
    for (int off = 16; off; off >>= 1)
        mx = fmaxf(mx, __shfl_xor_sync(0xffffffffu, mx, off));
    if (l == 0) atomicMax(&g_absmax_bits, __float_as_uint(mx));

    // ---- grid barrier: absmax final ----
    __syncthreads();
    __threadfence();
    if (tid == 0) {
        atomicAdd(&g_barcnt, 1u);
        while (*((volatile unsigned int*)&g_barcnt) < nblk) __nanosleep(64);
    }
    __syncthreads();

    // ---- quantize from registers, store out ----
    float absmax = __uint_as_float(*((volatile unsigned int*)&g_absmax_bits));
    float qscale = qs[0];
    float inv = (absmax > 0.0f) ? (1.0f / absmax) : 0.0f;
    float osc = absmax * qscale;

#pragma unroll
    for (int rt = 0; rt < NT; rt++)
#pragma unroll
        for (int nt = 0; nt < 2; nt++) {
            float4 v = S[rt][nt];
            float2 o0, o1;
            if (absmax > 0.0f) {
                o0 = make_float2(nf4_bs(v.x * inv) * osc, nf4_bs(v.y * inv) * osc);
                o1 = make_float2(nf4_bs(v.z * inv) * osc, nf4_bs(v.w * inv) * osc);
            } else {
                o0 = make_float2(v.x * qscale, v.y * qscale);
                o1 = make_float2(v.z * qscale, v.w * qscale);
            }
            int row = (t0 + rt) * 16 + r_in;
            int col = wid * 16 + nt * 8 + cq * 2;
            *(float2*)&out[(size_t)row * NCOL + col]       = o0;
            *(float2*)&out[(size_t)(row + 8) * NCOL + col] = o1;
        }
}

__global__ void __launch_bounds__(128, 1) k_gemm(const float* __restrict__ x,
                                                 float* __restrict__ out,
                                                 const float* __restrict__ qs) {
    extern __shared__ char smem[];
    uint32_t sbA = (uint32_t)__cvta_generic_to_shared(smem);
    uint32_t sbB = sbA + 2 * SMA_SZ;
    unsigned int nblk = gridDim.x;

    int t0 = (int)(((long long)blockIdx.x * MT16) / nblk);
    int t1 = (int)(((long long)(blockIdx.x + 1) * MT16) / nblk);
    int nt = t1 - t0;

    if (nt == 7)      gemm_body<7>(x, out, qs, t0, sbA, sbB, nblk);
    else if (nt == 6) gemm_body<6>(x, out, qs, t0, sbA, sbB, nblk);
    else if (nt == 5) gemm_body<5>(x, out, qs, t0, sbA, sbB, nblk);
    else if (nt == 4) gemm_body<4>(x, out, qs, t0, sbA, sbB, nblk);
    else if (nt == 3) gemm_body<3>(x, out, qs, t0, sbA, sbB, nblk);
    else if (nt == 2) gemm_body<2>(x, out, qs, t0, sbA, sbB, nblk);
    else if (nt == 1) gemm_body<1>(x, out, qs, t0, sbA, sbB, nblk);
    else {
        // nt == 0: still must participate in the barrier
        __syncthreads();
        if (threadIdx.x == 0) {
            atomicAdd(&g_barcnt, 1u);
            while (*((volatile unsigned int*)&g_barcnt) < nblk) __nanosleep(64);
        }
        __syncthreads();
    }
}

// ---------------- launch ----------------
extern "C" void kernel_launch(void* const* d_in, const int* in_sizes, int n_in,
                              void* d_out, int out_size) {
    const float* x  = (const float*)d_in[0];   // [4,4096,4096]
    const float* A  = (const float*)d_in[1];   // [64,64]
    const float* Bm = (const float*)d_in[2];   // [4096,64]
    const float* qs = (const float*)d_in[3];   // [1]
    const float* ri = (const float*)d_in[4];   // [64]
    float* out = (float*)d_out;

    int dev = 0, nsm = 148;
    cudaGetDevice(&dev);
    cudaDeviceGetAttribute(&nsm, cudaDevAttrMultiProcessorCount, dev);

    cudaFuncSetAttribute(k_gemm, cudaFuncAttributeMaxDynamicSharedMemorySize, SM_TOTAL);

    k_w<<<DK / 4, dim3(64, 4)>>>(Bm, A, ri);
    k_gemm<<<nsm, 128, SM_TOTAL>>>(x, out, qs);
}